// round 9
// baseline (speedup 1.0000x reference)
#include <cuda_runtime.h>
#include <cuda_fp16.h>
#include <cstdint>
#include <math.h>

// ---------------------------------------------------------------------------
// Problem dims
// ---------------------------------------------------------------------------
#define T_STEPS 128
#define B_SZ    512
#define IN_SZ   784
#define H_SZ    2048
#define OUT_SZ  10
#define MB      (T_STEPS * B_SZ)          // 65536 GEMM rows
#define BH      (B_SZ * H_SZ)             // 1048576 neurons

#define KTP     800                       // padded K halfs per region (zeros 784..799)
#define KAP     1600                      // packed row stride in halfs: [hi|lo]

// GEMM tiling: 256x128 CTA, 8 warps (4x2) of 64x64 warp tiles, BK=32
#define BM_T    256
#define BN_T    128
#define BK_T    32                        // K per stage = two m16n8k16 sub-chunks
#define NSTG    25                        // 800 / 32
#define RB      80                        // smem row bytes (64B data + 16B pad)
#define REG_A   (256 * RB)                // 20480 B (one of Ahi/Alo)
#define REG_B   (128 * RB)                // 10240 B (one of Bhi/Blo)
#define OFF_AH  0
#define OFF_AL  REG_A
#define OFF_BH  (2 * REG_A)
#define OFF_BL  (2 * REG_A + REG_B)
#define STAGEB  (2 * REG_A + 2 * REG_B)   // 61440 B per stage
#define SMEMB   (3 * STAGEB)              // 184320 B (3 stages)

// Scratch (device globals — no runtime allocation allowed)
__device__ float  g_cur[(size_t)MB * H_SZ];    // 512 MB
__device__ __half g_A[(size_t)MB * KAP];       // 210 MB packed [hi|lo] X (fp16)
__device__ __half g_B[(size_t)H_SZ * KAP];     // 6.6 MB packed [hi|lo] W1
__device__ float  g_S[(size_t)B_SZ * H_SZ];    // weighted spike sums
__device__ float  g_coef[T_STEPS];

// ---------------------------------------------------------------------------
// PTX helpers (arch-agnostic only: cp.async + mma.sync)
// ---------------------------------------------------------------------------
__device__ __forceinline__ uint32_t smem_u32(const void* p) {
    uint32_t a;
    asm("{ .reg .u64 t; cvta.to.shared.u64 t, %1; cvt.u32.u64 %0, t; }"
        : "=r"(a) : "l"(p));
    return a;
}
#define CP16(dst, src) \
    asm volatile("cp.async.cg.shared.global [%0], [%1], 16;" :: "r"(dst), "l"(src) : "memory")
#define CP_COMMIT() asm volatile("cp.async.commit_group;" ::: "memory")
#define CP_WAIT1()  asm volatile("cp.async.wait_group 1;" ::: "memory")

#define LDS32(reg, addr) \
    asm volatile("ld.shared.b32 %0, [%1];" : "=r"(reg) : "r"(addr))

// D += A*B  (m16n8k16, fp16 inputs packed f16x2 in b32 regs, fp32 accumulate)
#define MMA_F16(c, a, b)                                                       \
    asm volatile(                                                              \
        "mma.sync.aligned.m16n8k16.row.col.f32.f16.f16.f32 "                   \
        "{%0,%1,%2,%3}, {%4,%5,%6,%7}, {%8,%9}, {%0,%1,%2,%3};"                \
        : "+f"((c)[0]), "+f"((c)[1]), "+f"((c)[2]), "+f"((c)[3])               \
        : "r"((a)[0]), "r"((a)[1]), "r"((a)[2]), "r"((a)[3]),                  \
          "r"((b)[0]), "r"((b)[1]))

// ---------------------------------------------------------------------------
// Kernel 0: readout coefficients  c_t = 0.9^(127-t) - 0.8^(127-t)
// ---------------------------------------------------------------------------
__global__ void coef_kernel() {
    int t = threadIdx.x;
    if (t < T_STEPS) {
        float m = (float)(T_STEPS - 1 - t);
        g_coef[t] = powf(0.9f, m) - powf(0.8f, m);
    }
}

// ---------------------------------------------------------------------------
// Pack kernels: fp32 -> (hi, lo) fp16 pairs, K padded 784->800 with zeros.
// Trailing zero columns add exact +0.0f to accumulators -> bit-identical.
// ---------------------------------------------------------------------------
__global__ __launch_bounds__(256)
void packA_kernel(const float* __restrict__ x) {
    size_t m = blockIdx.x;
    const float* src = x + m * IN_SZ;
    __half* dst = g_A + m * KAP;
    for (int k = threadIdx.x; k < KTP; k += 256) {
        float v = (k < IN_SZ) ? src[k] : 0.0f;
        __half h = __float2half_rn(v);
        dst[k] = h;
        dst[KTP + k] = __float2half_rn(v - __half2float(h));
    }
}
__global__ __launch_bounds__(256)
void packB_kernel(const float* __restrict__ w) {
    size_t n = blockIdx.x;
    const float* src = w + n * IN_SZ;
    __half* dst = g_B + n * KAP;
    for (int k = threadIdx.x; k < KTP; k += 256) {
        float v = (k < IN_SZ) ? src[k] : 0.0f;
        __half h = __float2half_rn(v);
        dst[k] = h;
        dst[KTP + k] = __float2half_rn(v - __half2float(h));
    }
}

// ---------------------------------------------------------------------------
// GEMM: CUR[65536,2048] = X @ W1^T, fp16x3 emulation on mma.sync m16n8k16.
// 256x128 CTA tile, 8 warps (4x2) of 64x64, BK=32, 3-stage cp.async pipeline.
// Per stage: STS 48KB for 2.1 MMAC (2x better bytes/MAC than R7), 25 barriers
// per tile (vs 49). RB=80 rows: LDS32 + STS.128 both bank-conflict-free.
// Per-acc order (hh->hl->lh per k16, k ascending) unchanged -> bit-identical.
// ---------------------------------------------------------------------------
__global__ __launch_bounds__(256, 1)
void mma_kernel() {
    extern __shared__ __align__(16) char smem[];
    const uint32_t sbase = smem_u32(smem);

    const int tid  = threadIdx.x;
    const int wid  = tid >> 5;
    const int lane = tid & 31;
    const int lq   = lane >> 2;           // 0..7
    const int lr   = lane & 3;            // 0..3
    const int warp_m = wid & 3;           // 4 strips of 64 rows
    const int warp_n = wid >> 2;          // 2 strips of 64 cols

    const int n0 = blockIdx.x * BN_T;     // x fastest -> A-panel L2 reuse
    const int m0 = blockIdx.y * BM_T;

    // ---- producer mapping ----
    // A: thread t owns A row t (256 rows), 4 CP16 hi + 4 CP16 lo per stage.
    // B: threads 0-127 own Bhi row t, threads 128-255 own Blo row t-128 (4 CP16).
    const __half* ga = g_A + (size_t)(m0 + tid) * KAP;
    const int browi = tid & 127;
    const __half* gb = g_B + (size_t)(n0 + browi) * KAP + ((tid >> 7) ? KTP : 0);
    const uint32_t b_dst_reg = (tid >> 7) ? OFF_BL : OFF_BH;
    const uint32_t a_rowoff = (uint32_t)tid * RB;
    const uint32_t b_rowoff = b_dst_reg + (uint32_t)browi * RB;

    float acc[4][8][4];
#pragma unroll
    for (int mi = 0; mi < 4; mi++)
#pragma unroll
        for (int ni = 0; ni < 8; ni++)
#pragma unroll
            for (int q = 0; q < 4; q++) acc[mi][ni][q] = 0.0f;

    // fragment base byte-offsets within a region
    const uint32_t a_off0 = (uint32_t)(warp_m * 64 + lq) * RB + (uint32_t)lr * 4u;
    const uint32_t b_off0 = (uint32_t)(warp_n * 64 + lq) * RB + (uint32_t)lr * 4u;

#define LOAD_STAGE(buf, kc) do {                                               \
    uint32_t st = sbase + (uint32_t)(buf) * STAGEB;                            \
    const __half* ga_h = ga + (kc);                                            \
    const __half* gb_h = gb + (kc);                                            \
    _Pragma("unroll")                                                          \
    for (int j = 0; j < 4; j++) {                                              \
        CP16(st + OFF_AH + a_rowoff + (uint32_t)j * 16u, ga_h + j * 8);        \
        CP16(st + OFF_AL + a_rowoff + (uint32_t)j * 16u, ga_h + KTP + j * 8);  \
        CP16(st + b_rowoff + (uint32_t)j * 16u,          gb_h + j * 8);        \
    } } while (0)

    // prologue: stages 0,1 committed
    LOAD_STAGE(0, 0);  CP_COMMIT();
    LOAD_STAGE(1, 32); CP_COMMIT();

    for (int k = 0; k < NSTG; k++) {
        CP_WAIT1();                 // stage k resident (<=1 group outstanding)
        __syncthreads();            // all warps done with stage k-1 buffer

        // prefetch stage k+2 into buffer (k+2)%3 == (k-1)%3 (freed above)
        if (k + 2 < NSTG) LOAD_STAGE((k + 2) % 3, (k + 2) * BK_T);
        CP_COMMIT();                // always commit (empty ok) to keep count

        const uint32_t st = sbase + (uint32_t)(k % 3) * STAGEB;
        const uint32_t sa_h = st + OFF_AH + a_off0;
        const uint32_t sa_l = st + OFF_AL + a_off0;
        const uint32_t sb_h = st + OFF_BH + b_off0;
        const uint32_t sb_l = st + OFF_BL + b_off0;

        // two k16 sub-chunks per stage
#pragma unroll
        for (int c = 0; c < 2; c++) {
            const uint32_t co = (uint32_t)c * 32u;

            // ---- preload fragments for this sub-chunk (64 LDS32) ----
            uint32_t ah[4][4], al[4][4], bh[8][2], bl[8][2];
#pragma unroll
            for (int mi = 0; mi < 4; mi++) {
                uint32_t base = (uint32_t)mi * (16u * RB) + co;
                LDS32(ah[mi][0], sa_h + base);
                LDS32(ah[mi][1], sa_h + base + 8u * RB);
                LDS32(ah[mi][2], sa_h + base + 16u);
                LDS32(ah[mi][3], sa_h + base + 8u * RB + 16u);
                LDS32(al[mi][0], sa_l + base);
                LDS32(al[mi][1], sa_l + base + 8u * RB);
                LDS32(al[mi][2], sa_l + base + 16u);
                LDS32(al[mi][3], sa_l + base + 8u * RB + 16u);
            }
#pragma unroll
            for (int ni = 0; ni < 8; ni++) {
                uint32_t base = (uint32_t)ni * (8u * RB) + co;
                LDS32(bh[ni][0], sb_h + base);
                LDS32(bh[ni][1], sb_h + base + 16u);
                LDS32(bl[ni][0], sb_l + base);
                LDS32(bl[ni][1], sb_l + base + 16u);
            }

            // ---- 96 MMAs: term-outer; per-acc order hh -> hl -> lh ----
#pragma unroll
            for (int mi = 0; mi < 4; mi++)
#pragma unroll
                for (int ni = 0; ni < 8; ni++)
                    MMA_F16(acc[mi][ni], ah[mi], bh[ni]);   // hi*hi
#pragma unroll
            for (int mi = 0; mi < 4; mi++)
#pragma unroll
                for (int ni = 0; ni < 8; ni++)
                    MMA_F16(acc[mi][ni], ah[mi], bl[ni]);   // hi*lo
#pragma unroll
            for (int mi = 0; mi < 4; mi++)
#pragma unroll
                for (int ni = 0; ni < 8; ni++)
                    MMA_F16(acc[mi][ni], al[mi], bh[ni]);   // lo*hi
        }
    }

    // epilogue: write C (D frag: c0=[lq][2lr], c1=[lq][2lr+1],
    //                    c2=[lq+8][2lr], c3=[lq+8][2lr+1])
#pragma unroll
    for (int mi = 0; mi < 4; mi++) {
        const int gm = m0 + warp_m * 64 + mi * 16 + lq;
        float* r0 = g_cur + (size_t)gm * H_SZ + n0 + warp_n * 64 + lr * 2;
        float* r1 = r0 + 8 * H_SZ;
#pragma unroll
        for (int ni = 0; ni < 8; ni++) {
            *(float2*)(r0 + ni * 8) = make_float2(acc[mi][ni][0], acc[mi][ni][1]);
            *(float2*)(r1 + ni * 8) = make_float2(acc[mi][ni][2], acc[mi][ni][3]);
        }
    }
#undef LOAD_STAGE
}

// ---------------------------------------------------------------------------
// LIF scan: S = sum_t c_t * z_t   (per-neuron, state in registers)
// ---------------------------------------------------------------------------
__global__ __launch_bounds__(256)
void scan_kernel() {
    const int gid = blockIdx.x * blockDim.x + threadIdx.x;
    const float4* cur4 = (const float4*)g_cur;

    float v0 = 0.f, v1 = 0.f, v2 = 0.f, v3 = 0.f;
    float i0 = 0.f, i1 = 0.f, i2 = 0.f, i3 = 0.f;
    float s0 = 0.f, s1 = 0.f, s2 = 0.f, s3 = 0.f;

#pragma unroll 4
    for (int t = 0; t < T_STEPS; t++) {
        float4 c = __ldg(&cur4[(size_t)t * (BH / 4) + gid]);
        float coef = g_coef[t];
        float vd, id;
        vd = v0 + 0.1f * ((0.0f - v0) + i0); id = 0.8f * i0;
        if ((vd - 0.25f) > 0.0f) { v0 = 0.0f; s0 += coef; } else { v0 = vd; }
        i0 = id + c.x;
        vd = v1 + 0.1f * ((0.0f - v1) + i1); id = 0.8f * i1;
        if ((vd - 0.25f) > 0.0f) { v1 = 0.0f; s1 += coef; } else { v1 = vd; }
        i1 = id + c.y;
        vd = v2 + 0.1f * ((0.0f - v2) + i2); id = 0.8f * i2;
        if ((vd - 0.25f) > 0.0f) { v2 = 0.0f; s2 += coef; } else { v2 = vd; }
        i2 = id + c.z;
        vd = v3 + 0.1f * ((0.0f - v3) + i3); id = 0.8f * i3;
        if ((vd - 0.25f) > 0.0f) { v3 = 0.0f; s3 += coef; } else { v3 = vd; }
        i3 = id + c.w;
    }
    ((float4*)g_S)[gid] = make_float4(s0, s1, s2, s3);
}

// ---------------------------------------------------------------------------
// Readout: vo = S @ Wout^T
// ---------------------------------------------------------------------------
__global__ __launch_bounds__(256)
void readout_kernel(const float* __restrict__ Wout, float* __restrict__ out) {
    const int b = blockIdx.x;
    const int tid = threadIdx.x;
    float acc[OUT_SZ];
#pragma unroll
    for (int o = 0; o < OUT_SZ; o++) acc[o] = 0.0f;

    const float* srow = g_S + (size_t)b * H_SZ;
    for (int h = tid; h < H_SZ; h += 256) {
        float sv = srow[h];
#pragma unroll
        for (int o = 0; o < OUT_SZ; o++)
            acc[o] = fmaf(sv, __ldg(&Wout[o * H_SZ + h]), acc[o]);
    }
    __shared__ float red[OUT_SZ][8];
    const int lane = tid & 31, warp = tid >> 5;
#pragma unroll
    for (int o = 0; o < OUT_SZ; o++) {
        float v = acc[o];
#pragma unroll
        for (int off = 16; off; off >>= 1) v += __shfl_down_sync(0xffffffffu, v, off);
        if (lane == 0) red[o][warp] = v;
    }
    __syncthreads();
    if (tid < OUT_SZ) {
        float v = 0.0f;
#pragma unroll
        for (int w = 0; w < 8; w++) v += red[tid][w];
        out[b * OUT_SZ + tid] = v;
    }
}

// ---------------------------------------------------------------------------
extern "C" void kernel_launch(void* const* d_in, const int* in_sizes, int n_in,
                              void* d_out, int out_size) {
    const float* x    = (const float*)d_in[0];   // [128,512,784]
    const float* W1   = (const float*)d_in[1];   // [2048,784]
    const float* Wout = (const float*)d_in[2];   // [10,2048]
    float* out = (float*)d_out;                  // [512,10]

    coef_kernel<<<1, 128>>>();
    packA_kernel<<<MB, 256>>>(x);
    packB_kernel<<<H_SZ, 256>>>(W1);

    cudaFuncSetAttribute(mma_kernel, cudaFuncAttributeMaxDynamicSharedMemorySize, SMEMB);
    dim3 grid(H_SZ / BN_T, MB / BM_T);   // (16, 256), x fastest
    mma_kernel<<<grid, 256, SMEMB>>>();

    scan_kernel<<<BH / 4 / 256, 256>>>();
    readout_kernel<<<B_SZ, 256>>>(Wout, out);
}

// round 10
// speedup vs baseline: 1.2762x; 1.2762x over previous
#include <cuda_runtime.h>
#include <cuda_fp16.h>
#include <cstdint>
#include <math.h>

// ---------------------------------------------------------------------------
// Problem dims
// ---------------------------------------------------------------------------
#define T_STEPS 128
#define B_SZ    512
#define IN_SZ   784
#define H_SZ    2048
#define OUT_SZ  10
#define MB      (T_STEPS * B_SZ)          // 65536 GEMM rows
#define BH      (B_SZ * H_SZ)             // 1048576 neurons

#define KT      784                       // K elements
#define KAP     1568                      // packed row stride in halfs: [hi|lo]

// GEMM tiling: 128x128 CTA, 4 warps (2x2) of 64x64 warp tiles (R7 base)
#define BM_T    128
#define BN_T    128
#define BK_T    16                        // K per stage = one m16n8k16 MMA
#define NSTG    49                        // 784 / 16
#define RB      48                        // smem row bytes (32B data + 16B pad)
#define REGION  (128 * RB)                // 6144 B: one of {Ahi,Alo,Bhi,Blo}
#define STAGEB  (4 * REGION)              // 24576 B per stage
#define NSTAGE  3                         // pipeline stages (was 4) -> 3 CTAs/SM
#define SMEMB   (NSTAGE * STAGEB)         // 73728 B

// Scratch (device globals — no runtime allocation allowed)
__device__ float  g_cur[(size_t)MB * H_SZ];    // 512 MB
__device__ __half g_A[(size_t)MB * KAP];       // 205 MB packed [hi|lo] X (fp16)
__device__ __half g_B[(size_t)H_SZ * KAP];     // 6.4 MB packed [hi|lo] W1
__device__ float  g_S[(size_t)B_SZ * H_SZ];    // weighted spike sums
__device__ float  g_coef[T_STEPS];

// ---------------------------------------------------------------------------
// PTX helpers (arch-agnostic: cp.async + ldmatrix + mma.sync)
// ---------------------------------------------------------------------------
__device__ __forceinline__ uint32_t smem_u32(const void* p) {
    uint32_t a;
    asm("{ .reg .u64 t; cvta.to.shared.u64 t, %1; cvt.u32.u64 %0, t; }"
        : "=r"(a) : "l"(p));
    return a;
}
#define CP16(dst, src) \
    asm volatile("cp.async.cg.shared.global [%0], [%1], 16;" :: "r"(dst), "l"(src) : "memory")
#define CP_COMMIT() asm volatile("cp.async.commit_group;" ::: "memory")
#define CP_WAIT1()  asm volatile("cp.async.wait_group 1;" ::: "memory")

// ldmatrix x4: four 8x8 b16 matrices; per-lane row address in %4
#define LDSM4(r0, r1, r2, r3, addr)                                            \
    asm volatile("ldmatrix.sync.aligned.m8n8.x4.shared.b16 "                   \
                 "{%0,%1,%2,%3}, [%4];"                                        \
                 : "=r"(r0), "=r"(r1), "=r"(r2), "=r"(r3) : "r"(addr))

// D += A*B  (m16n8k16, fp16 inputs packed f16x2 in b32 regs, fp32 accumulate)
#define MMA_F16(c, a, b)                                                       \
    asm volatile(                                                              \
        "mma.sync.aligned.m16n8k16.row.col.f32.f16.f16.f32 "                   \
        "{%0,%1,%2,%3}, {%4,%5,%6,%7}, {%8,%9}, {%0,%1,%2,%3};"                \
        : "+f"((c)[0]), "+f"((c)[1]), "+f"((c)[2]), "+f"((c)[3])               \
        : "r"((a)[0]), "r"((a)[1]), "r"((a)[2]), "r"((a)[3]),                  \
          "r"((b)[0]), "r"((b)[1]))

// ---------------------------------------------------------------------------
// Kernel 0: readout coefficients  c_t = 0.9^(127-t) - 0.8^(127-t)
// ---------------------------------------------------------------------------
__global__ void coef_kernel() {
    int t = threadIdx.x;
    if (t < T_STEPS) {
        float m = (float)(T_STEPS - 1 - t);
        g_coef[t] = powf(0.9f, m) - powf(0.8f, m);
    }
}

// ---------------------------------------------------------------------------
// Pack kernels: split fp32 -> (hi, lo) fp16 pairs (11-bit limbs)
// ---------------------------------------------------------------------------
__global__ __launch_bounds__(256)
void packA_kernel(const float* __restrict__ x) {
    size_t m = blockIdx.x;
    const float* src = x + m * IN_SZ;
    __half* dst = g_A + m * KAP;
    for (int k = threadIdx.x; k < KT; k += 256) {
        float v = src[k];
        __half h = __float2half_rn(v);
        dst[k] = h;
        dst[KT + k] = __float2half_rn(v - __half2float(h));
    }
}
__global__ __launch_bounds__(256)
void packB_kernel(const float* __restrict__ w) {
    size_t n = blockIdx.x;
    const float* src = w + n * IN_SZ;
    __half* dst = g_B + n * KAP;
    for (int k = threadIdx.x; k < KT; k += 256) {
        float v = src[k];
        __half h = __float2half_rn(v);
        dst[k] = h;
        dst[KT + k] = __float2half_rn(v - __half2float(h));
    }
}

// ---------------------------------------------------------------------------
// GEMM: CUR[65536,2048] = X @ W1^T, fp16x3 emulation on mma.sync m16n8k16.
// R7 base (128x128 CTA, 4 warps of 64x64, BK=16) with:
//  - 3-stage pipeline (74KB smem) -> 3 CTAs/SM for cross-CTA phase overlap
//  - ldmatrix.x4 fragment loads: 16 LDSM vs 64 LDS32 per warp-stage
// Per-acc order (hh->hl->lh per stage, stages ascending) -> bit-identical.
// ---------------------------------------------------------------------------
__global__ __launch_bounds__(128, 3)
void mma_kernel() {
    extern __shared__ __align__(16) char smem[];
    const uint32_t sbase = smem_u32(smem);

    const int tid  = threadIdx.x;
    const int wid  = tid >> 5;
    const int lane = tid & 31;
    const int lq   = lane >> 2;           // 0..7
    const int lr   = lane & 3;            // 0..3
    const int warp_m = wid & 1;           // 2 strips of 64 rows
    const int warp_n = wid >> 1;          // 2 strips of 64 cols

    const int n0 = blockIdx.x * BN_T;     // x fastest -> A-tile L2 reuse
    const int m0 = blockIdx.y * BM_T;

    // ---- producer mapping: thread t owns row t of all 4 regions ----
    const int prow = tid;                 // 0..127
    const __half* ga = g_A + (size_t)(m0 + prow) * KAP;
    const __half* gb = g_B + (size_t)(n0 + prow) * KAP;
    const uint32_t prowoff = (uint32_t)prow * RB;

    float acc[4][8][4];
#pragma unroll
    for (int mi = 0; mi < 4; mi++)
#pragma unroll
        for (int ni = 0; ni < 8; ni++)
#pragma unroll
            for (int q = 0; q < 4; q++) acc[mi][ni][q] = 0.0f;

    // ---- ldmatrix per-lane addresses (region-relative) ----
    // A x4: lanes 0-7 -> rows 0-7 (k0-7), 8-15 -> rows 8-15 (k0-7),
    //       16-23 -> rows 0-7 (k8-15), 24-31 -> rows 8-15 (k8-15)
    const uint32_t a_row = (uint32_t)(warp_m * 64 + (lane & 7) + ((lane >> 3) & 1) * 8);
    const uint32_t a_lm  = a_row * RB + (uint32_t)((lane >> 4) & 1) * 16u;
    // B x4 (pair p covers ni=2p,2p+1):
    //   lanes 0-7 -> n rows 0-7 (k0-7), 8-15 -> n rows 0-7 (k8-15),
    //   16-23 -> n rows 8-15 (k0-7), 24-31 -> n rows 8-15 (k8-15)
    const uint32_t b_g   = (uint32_t)(lane >> 3);
    const uint32_t b_row = (uint32_t)(warp_n * 64 + (b_g >> 1) * 8 + (lane & 7));
    const uint32_t b_lm  = b_row * RB + (b_g & 1u) * 16u;

#define LOAD_STAGE(buf, kc) do {                                               \
    uint32_t st = sbase + (uint32_t)(buf) * STAGEB;                            \
    const __half* ga_h = ga + (kc);                                            \
    const __half* gb_h = gb + (kc);                                            \
    CP16(st + 0 * REGION + prowoff,       ga_h);                               \
    CP16(st + 0 * REGION + prowoff + 16u, ga_h + 8);                           \
    CP16(st + 1 * REGION + prowoff,       ga_h + KT);                          \
    CP16(st + 1 * REGION + prowoff + 16u, ga_h + KT + 8);                      \
    CP16(st + 2 * REGION + prowoff,       gb_h);                               \
    CP16(st + 2 * REGION + prowoff + 16u, gb_h + 8);                           \
    CP16(st + 3 * REGION + prowoff,       gb_h + KT);                          \
    CP16(st + 3 * REGION + prowoff + 16u, gb_h + KT + 8);                      \
    } while (0)

    // prologue: stages 0,1 committed
    LOAD_STAGE(0, 0);  CP_COMMIT();
    LOAD_STAGE(1, 16); CP_COMMIT();

    for (int k = 0; k < NSTG; k++) {
        CP_WAIT1();                 // stage k resident (<=1 group outstanding)
        __syncthreads();            // all warps done with stage k-1 buffer

        // prefetch stage k+2 into buffer (k+2)%3 == (k-1)%3 (freed above)
        if (k + 2 < NSTG) LOAD_STAGE((k + 2) % NSTAGE, (k + 2) * BK_T);
        CP_COMMIT();                // always commit (empty ok) to keep count

        const uint32_t st = sbase + (uint32_t)(k % NSTAGE) * STAGEB;

        // ---- fragment loads: 16 ldmatrix.x4 ----
        uint32_t ah[4][4], al[4][4], bh[8][2], bl[8][2];
#pragma unroll
        for (int mi = 0; mi < 4; mi++) {
            uint32_t off = (uint32_t)mi * (16u * RB) + a_lm;
            LDSM4(ah[mi][0], ah[mi][1], ah[mi][2], ah[mi][3], st + 0 * REGION + off);
            LDSM4(al[mi][0], al[mi][1], al[mi][2], al[mi][3], st + 1 * REGION + off);
        }
#pragma unroll
        for (int p = 0; p < 4; p++) {
            uint32_t off = (uint32_t)p * (16u * RB) + b_lm;
            LDSM4(bh[2*p][0], bh[2*p][1], bh[2*p+1][0], bh[2*p+1][1],
                  st + 2 * REGION + off);
            LDSM4(bl[2*p][0], bl[2*p][1], bl[2*p+1][0], bl[2*p+1][1],
                  st + 3 * REGION + off);
        }

        // ---- 96 MMAs: term-outer; per-acc order hh -> hl -> lh ----
#pragma unroll
        for (int mi = 0; mi < 4; mi++)
#pragma unroll
            for (int ni = 0; ni < 8; ni++)
                MMA_F16(acc[mi][ni], ah[mi], bh[ni]);   // hi*hi
#pragma unroll
        for (int mi = 0; mi < 4; mi++)
#pragma unroll
            for (int ni = 0; ni < 8; ni++)
                MMA_F16(acc[mi][ni], ah[mi], bl[ni]);   // hi*lo
#pragma unroll
        for (int mi = 0; mi < 4; mi++)
#pragma unroll
            for (int ni = 0; ni < 8; ni++)
                MMA_F16(acc[mi][ni], al[mi], bh[ni]);   // lo*hi
    }

    // epilogue: write C (D frag: c0=[lq][2lr], c1=[lq][2lr+1],
    //                    c2=[lq+8][2lr], c3=[lq+8][2lr+1])
#pragma unroll
    for (int mi = 0; mi < 4; mi++) {
        const int gm = m0 + warp_m * 64 + mi * 16 + lq;
        float* r0 = g_cur + (size_t)gm * H_SZ + n0 + warp_n * 64 + lr * 2;
        float* r1 = r0 + 8 * H_SZ;
#pragma unroll
        for (int ni = 0; ni < 8; ni++) {
            *(float2*)(r0 + ni * 8) = make_float2(acc[mi][ni][0], acc[mi][ni][1]);
            *(float2*)(r1 + ni * 8) = make_float2(acc[mi][ni][2], acc[mi][ni][3]);
        }
    }
#undef LOAD_STAGE
}

// ---------------------------------------------------------------------------
// LIF scan: S = sum_t c_t * z_t   (per-neuron, state in registers)
// ---------------------------------------------------------------------------
__global__ __launch_bounds__(256)
void scan_kernel() {
    const int gid = blockIdx.x * blockDim.x + threadIdx.x;
    const float4* cur4 = (const float4*)g_cur;

    float v0 = 0.f, v1 = 0.f, v2 = 0.f, v3 = 0.f;
    float i0 = 0.f, i1 = 0.f, i2 = 0.f, i3 = 0.f;
    float s0 = 0.f, s1 = 0.f, s2 = 0.f, s3 = 0.f;

#pragma unroll 4
    for (int t = 0; t < T_STEPS; t++) {
        float4 c = __ldg(&cur4[(size_t)t * (BH / 4) + gid]);
        float coef = g_coef[t];
        float vd, id;
        vd = v0 + 0.1f * ((0.0f - v0) + i0); id = 0.8f * i0;
        if ((vd - 0.25f) > 0.0f) { v0 = 0.0f; s0 += coef; } else { v0 = vd; }
        i0 = id + c.x;
        vd = v1 + 0.1f * ((0.0f - v1) + i1); id = 0.8f * i1;
        if ((vd - 0.25f) > 0.0f) { v1 = 0.0f; s1 += coef; } else { v1 = vd; }
        i1 = id + c.y;
        vd = v2 + 0.1f * ((0.0f - v2) + i2); id = 0.8f * i2;
        if ((vd - 0.25f) > 0.0f) { v2 = 0.0f; s2 += coef; } else { v2 = vd; }
        i2 = id + c.z;
        vd = v3 + 0.1f * ((0.0f - v3) + i3); id = 0.8f * i3;
        if ((vd - 0.25f) > 0.0f) { v3 = 0.0f; s3 += coef; } else { v3 = vd; }
        i3 = id + c.w;
    }
    ((float4*)g_S)[gid] = make_float4(s0, s1, s2, s3);
}

// ---------------------------------------------------------------------------
// Readout: vo = S @ Wout^T
// ---------------------------------------------------------------------------
__global__ __launch_bounds__(256)
void readout_kernel(const float* __restrict__ Wout, float* __restrict__ out) {
    const int b = blockIdx.x;
    const int tid = threadIdx.x;
    float acc[OUT_SZ];
#pragma unroll
    for (int o = 0; o < OUT_SZ; o++) acc[o] = 0.0f;

    const float* srow = g_S + (size_t)b * H_SZ;
    for (int h = tid; h < H_SZ; h += 256) {
        float sv = srow[h];
#pragma unroll
        for (int o = 0; o < OUT_SZ; o++)
            acc[o] = fmaf(sv, __ldg(&Wout[o * H_SZ + h]), acc[o]);
    }
    __shared__ float red[OUT_SZ][8];
    const int lane = tid & 31, warp = tid >> 5;
#pragma unroll
    for (int o = 0; o < OUT_SZ; o++) {
        float v = acc[o];
#pragma unroll
        for (int off = 16; off; off >>= 1) v += __shfl_down_sync(0xffffffffu, v, off);
        if (lane == 0) red[o][warp] = v;
    }
    __syncthreads();
    if (tid < OUT_SZ) {
        float v = 0.0f;
#pragma unroll
        for (int w = 0; w < 8; w++) v += red[tid][w];
        out[b * OUT_SZ + tid] = v;
    }
}

// ---------------------------------------------------------------------------
extern "C" void kernel_launch(void* const* d_in, const int* in_sizes, int n_in,
                              void* d_out, int out_size) {
    const float* x    = (const float*)d_in[0];   // [128,512,784]
    const float* W1   = (const float*)d_in[1];   // [2048,784]
    const float* Wout = (const float*)d_in[2];   // [10,2048]
    float* out = (float*)d_out;                  // [512,10]

    coef_kernel<<<1, 128>>>();
    packA_kernel<<<MB, 256>>>(x);
    packB_kernel<<<H_SZ, 256>>>(W1);

    cudaFuncSetAttribute(mma_kernel, cudaFuncAttributeMaxDynamicSharedMemorySize, SMEMB);
    dim3 grid(H_SZ / BN_T, MB / BM_T);   // (16, 512), x fastest
    mma_kernel<<<grid, 128, SMEMB>>>();

    scan_kernel<<<BH / 4 / 256, 256>>>();
    readout_kernel<<<B_SZ, 256>>>(Wout, out);
}

// round 11
// speedup vs baseline: 1.4720x; 1.1535x over previous
#include <cuda_runtime.h>
#include <cuda_fp16.h>
#include <cstdint>
#include <math.h>

// ---------------------------------------------------------------------------
// Problem dims
// ---------------------------------------------------------------------------
#define T_STEPS 128
#define B_SZ    512
#define IN_SZ   784
#define H_SZ    2048
#define OUT_SZ  10
#define MB      (T_STEPS * B_SZ)          // 65536 GEMM rows
#define BH      (B_SZ * H_SZ)             // 1048576 neurons

#define KT      784                       // K elements
#define KAP     1568                      // packed row stride in halfs: [hi|lo]

// GEMM tiling: 128x128 CTA, 4 warps (2x2) of 64x64 warp tiles (R7 base)
#define BM_T    128
#define BN_T    128
#define BK_T    16                        // K per stage = one m16n8k16 MMA
#define NSTG    49                        // 784 / 16
#define RB      48                        // smem row bytes (32B data + 16B pad)
#define REGION  (128 * RB)                // 6144 B: one of {Ahi,Alo,Bhi,Blo}
#define STAGEB  (4 * REGION)              // 24576 B per stage
#define NSTAGE  3                         // 3 stages -> 73728 B -> 3 CTAs/SM
#define SMEMB   (NSTAGE * STAGEB)

// Scratch (device globals — no runtime allocation allowed)
__device__ float  g_cur[(size_t)MB * H_SZ];    // 512 MB
__device__ __half g_A[(size_t)MB * KAP];       // 205 MB packed [hi|lo] X (fp16)
__device__ __half g_B[(size_t)H_SZ * KAP];     // 6.4 MB packed [hi|lo] W1
__device__ float  g_S[(size_t)B_SZ * H_SZ];    // weighted spike sums
__device__ float  g_coef[T_STEPS];

// ---------------------------------------------------------------------------
// PTX helpers (arch-agnostic only: cp.async + mma.sync)
// ---------------------------------------------------------------------------
__device__ __forceinline__ uint32_t smem_u32(const void* p) {
    uint32_t a;
    asm("{ .reg .u64 t; cvta.to.shared.u64 t, %1; cvt.u32.u64 %0, t; }"
        : "=r"(a) : "l"(p));
    return a;
}
#define CP16(dst, src) \
    asm volatile("cp.async.cg.shared.global [%0], [%1], 16;" :: "r"(dst), "l"(src) : "memory")
#define CP_COMMIT() asm volatile("cp.async.commit_group;" ::: "memory")
#define CP_WAIT1()  asm volatile("cp.async.wait_group 1;" ::: "memory")

#define LDS32(reg, addr) \
    asm volatile("ld.shared.b32 %0, [%1];" : "=r"(reg) : "r"(addr))

// D += A*B  (m16n8k16, fp16 inputs packed f16x2 in b32 regs, fp32 accumulate)
#define MMA_F16(c, a, b)                                                       \
    asm volatile(                                                              \
        "mma.sync.aligned.m16n8k16.row.col.f32.f16.f16.f32 "                   \
        "{%0,%1,%2,%3}, {%4,%5,%6,%7}, {%8,%9}, {%0,%1,%2,%3};"                \
        : "+f"((c)[0]), "+f"((c)[1]), "+f"((c)[2]), "+f"((c)[3])               \
        : "r"((a)[0]), "r"((a)[1]), "r"((a)[2]), "r"((a)[3]),                  \
          "r"((b)[0]), "r"((b)[1]))

// ---------------------------------------------------------------------------
// Kernel 0: readout coefficients  c_t = 0.9^(127-t) - 0.8^(127-t)
// ---------------------------------------------------------------------------
__global__ void coef_kernel() {
    int t = threadIdx.x;
    if (t < T_STEPS) {
        float m = (float)(T_STEPS - 1 - t);
        g_coef[t] = powf(0.9f, m) - powf(0.8f, m);
    }
}

// ---------------------------------------------------------------------------
// Pack kernels: split fp32 -> (hi, lo) fp16 pairs (11-bit limbs)
// ---------------------------------------------------------------------------
__global__ __launch_bounds__(256)
void packA_kernel(const float* __restrict__ x) {
    size_t m = blockIdx.x;
    const float* src = x + m * IN_SZ;
    __half* dst = g_A + m * KAP;
    for (int k = threadIdx.x; k < KT; k += 256) {
        float v = src[k];
        __half h = __float2half_rn(v);
        dst[k] = h;
        dst[KT + k] = __float2half_rn(v - __half2float(h));
    }
}
__global__ __launch_bounds__(256)
void packB_kernel(const float* __restrict__ w) {
    size_t n = blockIdx.x;
    const float* src = w + n * IN_SZ;
    __half* dst = g_B + n * KAP;
    for (int k = threadIdx.x; k < KT; k += 256) {
        float v = src[k];
        __half h = __float2half_rn(v);
        dst[k] = h;
        dst[KT + k] = __float2half_rn(v - __half2float(h));
    }
}

// ---------------------------------------------------------------------------
// GEMM: CUR[65536,2048] = X @ W1^T, fp16x3 emulation on mma.sync m16n8k16.
// R7 base (128x128 CTA, 4 warps of 64x64, BK=16, LDS32 fragment loads) with
// ONE change: 3-stage pipeline (74KB smem) -> 3 CTAs/SM. R9 showed ldmatrix
// costs ~2x crossbar time here, so fragment loads stay LDS32 (R7 pattern).
// Per-acc order (hh->hl->lh per stage, stages ascending) -> bit-identical.
// ---------------------------------------------------------------------------
__global__ __launch_bounds__(128, 3)
void mma_kernel() {
    extern __shared__ __align__(16) char smem[];
    const uint32_t sbase = smem_u32(smem);

    const int tid  = threadIdx.x;
    const int wid  = tid >> 5;
    const int lane = tid & 31;
    const int lq   = lane >> 2;           // 0..7
    const int lr   = lane & 3;            // 0..3
    const int warp_m = wid & 1;           // 2 strips of 64 rows
    const int warp_n = wid >> 1;          // 2 strips of 64 cols

    const int n0 = blockIdx.x * BN_T;     // x fastest -> A-tile L2 reuse
    const int m0 = blockIdx.y * BM_T;

    // ---- producer mapping: thread t owns row t of all 4 regions ----
    const int prow = tid;                 // 0..127
    const __half* ga = g_A + (size_t)(m0 + prow) * KAP;
    const __half* gb = g_B + (size_t)(n0 + prow) * KAP;
    const uint32_t prowoff = (uint32_t)prow * RB;

    float acc[4][8][4];
#pragma unroll
    for (int mi = 0; mi < 4; mi++)
#pragma unroll
        for (int ni = 0; ni < 8; ni++)
#pragma unroll
            for (int q = 0; q < 4; q++) acc[mi][ni][q] = 0.0f;

    // fragment base byte-offsets within a region
    const uint32_t a_off0 = (uint32_t)(warp_m * 64 + lq) * RB + (uint32_t)lr * 4u;
    const uint32_t b_off0 = (uint32_t)(warp_n * 64 + lq) * RB + (uint32_t)lr * 4u;

#define LOAD_STAGE(buf, kc) do {                                               \
    uint32_t st = sbase + (uint32_t)(buf) * STAGEB;                            \
    const __half* ga_h = ga + (kc);                                            \
    const __half* gb_h = gb + (kc);                                            \
    CP16(st + 0 * REGION + prowoff,       ga_h);                               \
    CP16(st + 0 * REGION + prowoff + 16u, ga_h + 8);                           \
    CP16(st + 1 * REGION + prowoff,       ga_h + KT);                          \
    CP16(st + 1 * REGION + prowoff + 16u, ga_h + KT + 8);                      \
    CP16(st + 2 * REGION + prowoff,       gb_h);                               \
    CP16(st + 2 * REGION + prowoff + 16u, gb_h + 8);                           \
    CP16(st + 3 * REGION + prowoff,       gb_h + KT);                          \
    CP16(st + 3 * REGION + prowoff + 16u, gb_h + KT + 8);                      \
    } while (0)

    // prologue: stages 0,1 committed
    LOAD_STAGE(0, 0);  CP_COMMIT();
    LOAD_STAGE(1, 16); CP_COMMIT();

    for (int k = 0; k < NSTG; k++) {
        CP_WAIT1();                 // stage k resident (<=1 group outstanding)
        __syncthreads();            // all warps done with stage k-1 buffer

        // prefetch stage k+2 into buffer (k+2)%3 == (k-1)%3 (freed above)
        if (k + 2 < NSTG) LOAD_STAGE((k + 2) % NSTAGE, (k + 2) * BK_T);
        CP_COMMIT();                // always commit (empty ok) to keep count

        const uint32_t st = sbase + (uint32_t)(k % NSTAGE) * STAGEB;
        const uint32_t sa_h = st + 0 * REGION + a_off0;
        const uint32_t sa_l = st + 1 * REGION + a_off0;
        const uint32_t sb_h = st + 2 * REGION + b_off0;
        const uint32_t sb_l = st + 3 * REGION + b_off0;

        // ---- preload all fragments (64 LDS32, R7 pattern) ----
        uint32_t ah[4][4], al[4][4], bh[8][2], bl[8][2];
#pragma unroll
        for (int mi = 0; mi < 4; mi++) {
            uint32_t base = (uint32_t)mi * (16u * RB);
            LDS32(ah[mi][0], sa_h + base);
            LDS32(ah[mi][1], sa_h + base + 8u * RB);
            LDS32(ah[mi][2], sa_h + base + 16u);
            LDS32(ah[mi][3], sa_h + base + 8u * RB + 16u);
            LDS32(al[mi][0], sa_l + base);
            LDS32(al[mi][1], sa_l + base + 8u * RB);
            LDS32(al[mi][2], sa_l + base + 16u);
            LDS32(al[mi][3], sa_l + base + 8u * RB + 16u);
        }
#pragma unroll
        for (int ni = 0; ni < 8; ni++) {
            uint32_t base = (uint32_t)ni * (8u * RB);
            LDS32(bh[ni][0], sb_h + base);
            LDS32(bh[ni][1], sb_h + base + 16u);
            LDS32(bl[ni][0], sb_l + base);
            LDS32(bl[ni][1], sb_l + base + 16u);
        }

        // ---- 96 MMAs: term-outer; per-acc order hh -> hl -> lh ----
#pragma unroll
        for (int mi = 0; mi < 4; mi++)
#pragma unroll
            for (int ni = 0; ni < 8; ni++)
                MMA_F16(acc[mi][ni], ah[mi], bh[ni]);   // hi*hi
#pragma unroll
        for (int mi = 0; mi < 4; mi++)
#pragma unroll
            for (int ni = 0; ni < 8; ni++)
                MMA_F16(acc[mi][ni], ah[mi], bl[ni]);   // hi*lo
#pragma unroll
        for (int mi = 0; mi < 4; mi++)
#pragma unroll
            for (int ni = 0; ni < 8; ni++)
                MMA_F16(acc[mi][ni], al[mi], bh[ni]);   // lo*hi
    }

    // epilogue: write C (D frag: c0=[lq][2lr], c1=[lq][2lr+1],
    //                    c2=[lq+8][2lr], c3=[lq+8][2lr+1])
#pragma unroll
    for (int mi = 0; mi < 4; mi++) {
        const int gm = m0 + warp_m * 64 + mi * 16 + lq;
        float* r0 = g_cur + (size_t)gm * H_SZ + n0 + warp_n * 64 + lr * 2;
        float* r1 = r0 + 8 * H_SZ;
#pragma unroll
        for (int ni = 0; ni < 8; ni++) {
            *(float2*)(r0 + ni * 8) = make_float2(acc[mi][ni][0], acc[mi][ni][1]);
            *(float2*)(r1 + ni * 8) = make_float2(acc[mi][ni][2], acc[mi][ni][3]);
        }
    }
#undef LOAD_STAGE
}

// ---------------------------------------------------------------------------
// LIF scan: S = sum_t c_t * z_t   (per-neuron, state in registers)
// ---------------------------------------------------------------------------
__global__ __launch_bounds__(256)
void scan_kernel() {
    const int gid = blockIdx.x * blockDim.x + threadIdx.x;
    const float4* cur4 = (const float4*)g_cur;

    float v0 = 0.f, v1 = 0.f, v2 = 0.f, v3 = 0.f;
    float i0 = 0.f, i1 = 0.f, i2 = 0.f, i3 = 0.f;
    float s0 = 0.f, s1 = 0.f, s2 = 0.f, s3 = 0.f;

#pragma unroll 4
    for (int t = 0; t < T_STEPS; t++) {
        float4 c = __ldg(&cur4[(size_t)t * (BH / 4) + gid]);
        float coef = g_coef[t];
        float vd, id;
        vd = v0 + 0.1f * ((0.0f - v0) + i0); id = 0.8f * i0;
        if ((vd - 0.25f) > 0.0f) { v0 = 0.0f; s0 += coef; } else { v0 = vd; }
        i0 = id + c.x;
        vd = v1 + 0.1f * ((0.0f - v1) + i1); id = 0.8f * i1;
        if ((vd - 0.25f) > 0.0f) { v1 = 0.0f; s1 += coef; } else { v1 = vd; }
        i1 = id + c.y;
        vd = v2 + 0.1f * ((0.0f - v2) + i2); id = 0.8f * i2;
        if ((vd - 0.25f) > 0.0f) { v2 = 0.0f; s2 += coef; } else { v2 = vd; }
        i2 = id + c.z;
        vd = v3 + 0.1f * ((0.0f - v3) + i3); id = 0.8f * i3;
        if ((vd - 0.25f) > 0.0f) { v3 = 0.0f; s3 += coef; } else { v3 = vd; }
        i3 = id + c.w;
    }
    ((float4*)g_S)[gid] = make_float4(s0, s1, s2, s3);
}

// ---------------------------------------------------------------------------
// Readout: vo = S @ Wout^T
// ---------------------------------------------------------------------------
__global__ __launch_bounds__(256)
void readout_kernel(const float* __restrict__ Wout, float* __restrict__ out) {
    const int b = blockIdx.x;
    const int tid = threadIdx.x;
    float acc[OUT_SZ];
#pragma unroll
    for (int o = 0; o < OUT_SZ; o++) acc[o] = 0.0f;

    const float* srow = g_S + (size_t)b * H_SZ;
    for (int h = tid; h < H_SZ; h += 256) {
        float sv = srow[h];
#pragma unroll
        for (int o = 0; o < OUT_SZ; o++)
            acc[o] = fmaf(sv, __ldg(&Wout[o * H_SZ + h]), acc[o]);
    }
    __shared__ float red[OUT_SZ][8];
    const int lane = tid & 31, warp = tid >> 5;
#pragma unroll
    for (int o = 0; o < OUT_SZ; o++) {
        float v = acc[o];
#pragma unroll
        for (int off = 16; off; off >>= 1) v += __shfl_down_sync(0xffffffffu, v, off);
        if (lane == 0) red[o][warp] = v;
    }
    __syncthreads();
    if (tid < OUT_SZ) {
        float v = 0.0f;
#pragma unroll
        for (int w = 0; w < 8; w++) v += red[tid][w];
        out[b * OUT_SZ + tid] = v;
    }
}

// ---------------------------------------------------------------------------
extern "C" void kernel_launch(void* const* d_in, const int* in_sizes, int n_in,
                              void* d_out, int out_size) {
    const float* x    = (const float*)d_in[0];   // [128,512,784]
    const float* W1   = (const float*)d_in[1];   // [2048,784]
    const float* Wout = (const float*)d_in[2];   // [10,2048]
    float* out = (float*)d_out;                  // [512,10]

    coef_kernel<<<1, 128>>>();
    packA_kernel<<<MB, 256>>>(x);
    packB_kernel<<<H_SZ, 256>>>(W1);

    cudaFuncSetAttribute(mma_kernel, cudaFuncAttributeMaxDynamicSharedMemorySize, SMEMB);
    dim3 grid(H_SZ / BN_T, MB / BM_T);   // (16, 512), x fastest
    mma_kernel<<<grid, 128, SMEMB>>>();

    scan_kernel<<<BH / 4 / 256, 256>>>();
    readout_kernel<<<B_SZ, 256>>>(Wout, out);
}